// round 1
// baseline (speedup 1.0000x reference)
#include <cuda_runtime.h>
#include <math.h>

// Problem constants
#define BB   4
#define SS   2048
#define DD   1024
#define HH   16
#define HDIM 64
// M = B*S = 8192, N = K = 1024 for all projection GEMMs

// Scratch (allocation-free rule: __device__ globals)
__device__ float g_Q[(size_t)8192 * 1024];
__device__ float g_K[(size_t)8192 * 1024];
__device__ float g_V[(size_t)8192 * 1024];
__device__ float g_X[(size_t)8192 * 1024];

// ---------------------------------------------------------------------------
// GEMM: C[M,N] = ( (A + Apos?) @ Bw + bias ) * scale
//   A: [8192, 1024] row-major; Apos: [2048, 1024] broadcast over batch (or null)
//   Bw: [1024, 1024] row-major; bias: [1024]
// 128x128x16 tile, 256 threads, 8x8 per-thread microtile, fp32.
// ---------------------------------------------------------------------------
__global__ __launch_bounds__(256, 2)
void gemm_kernel(const float* __restrict__ A, const float* __restrict__ Apos,
                 const float* __restrict__ Bw, const float* __restrict__ bias,
                 float* __restrict__ C, float scale)
{
    const int N = 1024, K = 1024;
    __shared__ float As[16][128];
    __shared__ float Bs[16][128];

    const int tid = threadIdx.x;
    const int tx = tid & 15;
    const int ty = tid >> 4;
    const int m0 = blockIdx.y * 128;
    const int n0 = blockIdx.x * 128;

    float acc[8][8];
#pragma unroll
    for (int i = 0; i < 8; ++i)
#pragma unroll
        for (int j = 0; j < 8; ++j) acc[i][j] = 0.f;

    for (int kb = 0; kb < K; kb += 16) {
        // Load A tile (transposed into As[k][m]), fused pos-emb add
#pragma unroll
        for (int it = 0; it < 2; ++it) {
            int slot = tid * 2 + it;          // 0..511
            int row  = slot >> 2;             // 0..127
            int c4   = (slot & 3) << 2;       // 0,4,8,12
            float4 av = *(const float4*)(A + (size_t)(m0 + row) * K + kb + c4);
            if (Apos) {
                float4 pv = *(const float4*)(Apos + (size_t)((m0 + row) & (SS - 1)) * K + kb + c4);
                av.x += pv.x; av.y += pv.y; av.z += pv.z; av.w += pv.w;
            }
            As[c4 + 0][row] = av.x;
            As[c4 + 1][row] = av.y;
            As[c4 + 2][row] = av.z;
            As[c4 + 3][row] = av.w;
        }
        // Load B tile
#pragma unroll
        for (int it = 0; it < 2; ++it) {
            int slot = tid * 2 + it;          // 0..511
            int row  = slot >> 5;             // 0..15
            int c4   = (slot & 31) << 2;      // 0..124
            *(float4*)&Bs[row][c4] = *(const float4*)(Bw + (size_t)(kb + row) * N + n0 + c4);
        }
        __syncthreads();

#pragma unroll
        for (int kk = 0; kk < 16; ++kk) {
            float ar[8], br[8];
            *(float4*)&ar[0] = *(const float4*)&As[kk][ty * 8];
            *(float4*)&ar[4] = *(const float4*)&As[kk][ty * 8 + 4];
            *(float4*)&br[0] = *(const float4*)&Bs[kk][tx * 8];
            *(float4*)&br[4] = *(const float4*)&Bs[kk][tx * 8 + 4];
#pragma unroll
            for (int i = 0; i < 8; ++i)
#pragma unroll
                for (int j = 0; j < 8; ++j)
                    acc[i][j] += ar[i] * br[j];
        }
        __syncthreads();
    }

    // Epilogue: (acc + bias) * scale
#pragma unroll
    for (int i = 0; i < 8; ++i) {
        int row = m0 + ty * 8 + i;
#pragma unroll
        for (int j4 = 0; j4 < 8; j4 += 4) {
            int col = n0 + tx * 8 + j4;
            float4 o;
            o.x = (acc[i][j4 + 0] + bias[col + 0]) * scale;
            o.y = (acc[i][j4 + 1] + bias[col + 1]) * scale;
            o.z = (acc[i][j4 + 2] + bias[col + 2]) * scale;
            o.w = (acc[i][j4 + 3] + bias[col + 3]) * scale;
            *(float4*)(C + (size_t)row * N + col) = o;
        }
    }
}

// ---------------------------------------------------------------------------
// Flash-style attention:
//   scores = Q·K^T + attention_bias[q,k] + attention_bias_kv[b,k]
//   online softmax over k, O = P·V, final O /= l
// Br=128 query rows/block, Bc=64 key cols/tile. 256 threads.
// Thread (ty,tx): owns score rows ty*8..+7, score cols tx*4..+3,
// and output rows ty*8..+7, head-dims tx*4..+3.
// ---------------------------------------------------------------------------
#define ATTN_SMEM_FLOATS (128 * 64 + 64 * 65 + 64 * 65 + 128 * 65)
#define ATTN_SMEM_BYTES  (ATTN_SMEM_FLOATS * 4)

__global__ __launch_bounds__(256)
void attn_kernel(const float* __restrict__ ab, const float* __restrict__ abkv)
{
    extern __shared__ float sm[];
    float* Qs = sm;                       // [128][64]   (stride 64; broadcast reads)
    float* Ks = Qs + 128 * 64;            // [64][65]
    float* Vs = Ks + 64 * 65;             // [64][65]
    float* Ps = Vs + 64 * 65;             // [128][65]

    const int tid = threadIdx.x;
    const int tx = tid & 15;
    const int ty = tid >> 4;
    const int b  = blockIdx.z;
    const int h  = blockIdx.y;
    const int q0 = blockIdx.x * 128;
    const int r0 = ty * 8;                // local row base
    const int c0 = tx * 4;                // local col / head-dim base

    // Load Q tile: 128 rows x 64 dims
    {
        const size_t baseQ = ((size_t)(b * SS + q0)) * DD + h * HDIM;
#pragma unroll
        for (int it = 0; it < 8; ++it) {
            int slot = tid * 8 + it;          // 0..2047
            int row  = slot >> 4;             // 0..127
            int c4   = (slot & 15) << 2;      // 0..60
            *(float4*)&Qs[row * 64 + c4] =
                *(const float4*)(g_Q + baseQ + (size_t)row * DD + c4);
        }
    }

    float acc[8][4];
#pragma unroll
    for (int i = 0; i < 8; ++i)
#pragma unroll
        for (int j = 0; j < 4; ++j) acc[i][j] = 0.f;
    float mrow[8], lrow[8];
#pragma unroll
    for (int i = 0; i < 8; ++i) { mrow[i] = -1e30f; lrow[i] = 0.f; }

    for (int kt = 0; kt < 32; ++kt) {
        const int k0 = kt * 64;
        // Load K and V tiles (64x64 each), padded stride 65 in smem
#pragma unroll
        for (int it = 0; it < 4; ++it) {
            int slot = tid * 4 + it;          // 0..1023
            int row  = slot >> 4;             // 0..63
            int c4   = (slot & 15) << 2;      // 0..60
            size_t g = ((size_t)(b * SS + k0 + row)) * DD + h * HDIM + c4;
            float4 kv = *(const float4*)(g_K + g);
            Ks[row * 65 + c4 + 0] = kv.x;
            Ks[row * 65 + c4 + 1] = kv.y;
            Ks[row * 65 + c4 + 2] = kv.z;
            Ks[row * 65 + c4 + 3] = kv.w;
            float4 vv = *(const float4*)(g_V + g);
            Vs[row * 65 + c4 + 0] = vv.x;
            Vs[row * 65 + c4 + 1] = vv.y;
            Vs[row * 65 + c4 + 2] = vv.z;
            Vs[row * 65 + c4 + 3] = vv.w;
        }
        __syncthreads();

        // S = Q · K^T  (8x4 per thread, k-loop over 64)
        float sacc[8][4];
#pragma unroll
        for (int i = 0; i < 8; ++i)
#pragma unroll
            for (int j = 0; j < 4; ++j) sacc[i][j] = 0.f;

#pragma unroll 4
        for (int k = 0; k < 64; ++k) {
            float qf[8], kf[4];
#pragma unroll
            for (int i = 0; i < 8; ++i) qf[i] = Qs[(r0 + i) * 64 + k];
#pragma unroll
            for (int j = 0; j < 4; ++j) kf[j] = Ks[(c0 + j) * 65 + k];
#pragma unroll
            for (int i = 0; i < 8; ++i)
#pragma unroll
                for (int j = 0; j < 4; ++j)
                    sacc[i][j] += qf[i] * kf[j];
        }

        // Bias + online softmax update
#pragma unroll
        for (int i = 0; i < 8; ++i) {
            const int r = r0 + i;
            float mx = -1e30f;
#pragma unroll
            for (int j = 0; j < 4; ++j) {
                float sv = sacc[i][j]
                         + ab[(size_t)(q0 + r) * SS + k0 + c0 + j]
                         + abkv[b * SS + k0 + c0 + j];
                sacc[i][j] = sv;
                mx = fmaxf(mx, sv);
            }
            // reduce max across the 16 col-owner lanes
#pragma unroll
            for (int off = 8; off; off >>= 1)
                mx = fmaxf(mx, __shfl_xor_sync(0xffffffffu, mx, off));
            float mnew = fmaxf(mrow[i], mx);
            float f = __expf(mrow[i] - mnew);
            float rs = 0.f;
#pragma unroll
            for (int j = 0; j < 4; ++j) {
                float p = __expf(sacc[i][j] - mnew);
                rs += p;
                Ps[(size_t)r * 65 + c0 + j] = p;
            }
#pragma unroll
            for (int off = 8; off; off >>= 1)
                rs += __shfl_xor_sync(0xffffffffu, rs, off);
            lrow[i] = lrow[i] * f + rs;
            mrow[i] = mnew;
#pragma unroll
            for (int j = 0; j < 4; ++j) acc[i][j] *= f;
        }
        __syncthreads();

        // O += P · V  (c-loop over 64)
#pragma unroll 4
        for (int c = 0; c < 64; ++c) {
            float pf[8], vf[4];
#pragma unroll
            for (int i = 0; i < 8; ++i) pf[i] = Ps[(r0 + i) * 65 + c];
#pragma unroll
            for (int j = 0; j < 4; ++j) vf[j] = Vs[c * 65 + c0 + j];
#pragma unroll
            for (int i = 0; i < 8; ++i)
#pragma unroll
                for (int j = 0; j < 4; ++j)
                    acc[i][j] += pf[i] * vf[j];
        }
        __syncthreads();
    }

    // Normalize and write X[b, q, h, hd]
#pragma unroll
    for (int i = 0; i < 8; ++i) {
        float inv = 1.f / lrow[i];
        int r = q0 + r0 + i;
        size_t base = ((size_t)(b * SS + r)) * DD + h * HDIM + c0;
#pragma unroll
        for (int j = 0; j < 4; ++j)
            g_X[base + j] = acc[i][j] * inv;
    }
}

// ---------------------------------------------------------------------------
extern "C" void kernel_launch(void* const* d_in, const int* in_sizes, int n_in,
                              void* d_out, int out_size)
{
    const float* x    = (const float*)d_in[0];
    const float* pq   = (const float*)d_in[1];
    const float* pk   = (const float*)d_in[2];
    const float* pv   = (const float*)d_in[3];
    const float* ab   = (const float*)d_in[4];
    const float* abkv = (const float*)d_in[5];
    const float* wq   = (const float*)d_in[6];
    const float* bq   = (const float*)d_in[7];
    const float* wk   = (const float*)d_in[8];
    const float* bk   = (const float*)d_in[9];
    const float* wv   = (const float*)d_in[10];
    const float* bv   = (const float*)d_in[11];
    const float* wo   = (const float*)d_in[12];
    const float* bo   = (const float*)d_in[13];
    float* out = (float*)d_out;

    float *Qp, *Kp, *Vp, *Xp;
    cudaGetSymbolAddress((void**)&Qp, g_Q);
    cudaGetSymbolAddress((void**)&Kp, g_K);
    cudaGetSymbolAddress((void**)&Vp, g_V);
    cudaGetSymbolAddress((void**)&Xp, g_X);

    dim3 gemm_grid(1024 / 128, 8192 / 128);   // (8, 64)

    // Q/K/V projections (pos-emb add fused into A load; 1/sqrt(HD) fused into Q)
    gemm_kernel<<<gemm_grid, 256>>>(x, pq, wq, bq, Qp, 0.125f);
    gemm_kernel<<<gemm_grid, 256>>>(x, pk, wk, bk, Kp, 1.0f);
    gemm_kernel<<<gemm_grid, 256>>>(x, pv, wv, bv, Vp, 1.0f);

    // Attention
    cudaFuncSetAttribute(attn_kernel, cudaFuncAttributeMaxDynamicSharedMemorySize,
                         ATTN_SMEM_BYTES);
    attn_kernel<<<dim3(SS / 128, HH, BB), 256, ATTN_SMEM_BYTES>>>(ab, abkv);

    // Output projection
    gemm_kernel<<<gemm_grid, 256>>>(Xp, nullptr, wo, bo, out, 1.0f);
}

// round 3
// speedup vs baseline: 1.2685x; 1.2685x over previous
#include <cuda_runtime.h>
#include <cuda_bf16.h>
#include <cstdint>
#include <math.h>

// Problem constants
#define BB   4
#define SS   2048
#define DD   1024
#define HH   16
#define HDIM 64

// Scratch (allocation-free rule: __device__ globals)
__device__ float g_Q[(size_t)8192 * 1024];
__device__ float g_K[(size_t)8192 * 1024];
__device__ float g_V[(size_t)8192 * 1024];
__device__ float g_X[(size_t)8192 * 1024];
// Pre-transposed + bf16-split weights: [4][N=1024][K=1024]
__device__ __nv_bfloat16 g_Whi[4][(size_t)1024 * 1024];
__device__ __nv_bfloat16 g_Wlo[4][(size_t)1024 * 1024];

// ---------------------------------------------------------------------------
// Helpers
// ---------------------------------------------------------------------------
__device__ __forceinline__ uint32_t smem_u32(const void* p) {
    uint32_t a;
    asm("{ .reg .u64 t; cvta.to.shared.u64 t, %1; cvt.u32.u64 %0, t; }" : "=r"(a) : "l"(p));
    return a;
}
__device__ __forceinline__ void ldm4(uint32_t* r, uint32_t addr) {
    asm volatile("ldmatrix.sync.aligned.m8n8.x4.shared.b16 {%0,%1,%2,%3}, [%4];"
                 : "=r"(r[0]), "=r"(r[1]), "=r"(r[2]), "=r"(r[3]) : "r"(addr));
}
__device__ __forceinline__ void mma_bf16(float* c, const uint32_t* a, uint32_t b0, uint32_t b1) {
    asm volatile(
        "mma.sync.aligned.m16n8k16.row.col.f32.bf16.bf16.f32 "
        "{%0,%1,%2,%3}, {%4,%5,%6,%7}, {%8,%9}, {%0,%1,%2,%3};"
        : "+f"(c[0]), "+f"(c[1]), "+f"(c[2]), "+f"(c[3])
        : "r"(a[0]), "r"(a[1]), "r"(a[2]), "r"(a[3]), "r"(b0), "r"(b1));
}
__device__ __forceinline__ uint32_t pack2(__nv_bfloat16 a, __nv_bfloat16 b) {
    __nv_bfloat162 t = __halves2bfloat162(a, b);
    return *(uint32_t*)&t;
}

// ---------------------------------------------------------------------------
// Prep: transpose W[K=1024][N=1024] -> [N][K], split into bf16 hi/lo
// ---------------------------------------------------------------------------
__global__ void prep_w_kernel(const float* __restrict__ W,
                              __nv_bfloat16* __restrict__ Whi,
                              __nv_bfloat16* __restrict__ Wlo)
{
    __shared__ float t[32][33];
    const int n0 = blockIdx.x * 32, k0 = blockIdx.y * 32;
    const int tx = threadIdx.x, ty = threadIdx.y;
#pragma unroll
    for (int i = 0; i < 4; ++i)
        t[ty + i * 8][tx] = W[(size_t)(k0 + ty + i * 8) * 1024 + n0 + tx];
    __syncthreads();
#pragma unroll
    for (int i = 0; i < 4; ++i) {
        int n = n0 + ty + i * 8;
        float x = t[tx][ty + i * 8];
        __nv_bfloat16 h = __float2bfloat16_rn(x);
        Whi[(size_t)n * 1024 + k0 + tx] = h;
        Wlo[(size_t)n * 1024 + k0 + tx] = __float2bfloat16_rn(x - __bfloat162float(h));
    }
}

// ---------------------------------------------------------------------------
// mma.sync bf16-split GEMM: C[8192,1024] = ((A[+Apos]) @ W + bias) * scale
// W pre-split, [N][K] K-major. Tile 128x128, K-chunk 32, 512 threads (16 warps,
// 32x32 warp tiles), double-buffered smem, 80B padded rows (conflict-free ldmatrix).
// ---------------------------------------------------------------------------
#define ROWB   80            // bytes per 32-element bf16 row (64 data + 16 pad)
#define AHI_O  0
#define ALO_O  10240
#define BHI_O  20480
#define BLO_O  30720
#define STAGEB 40960
#define GEMM_SMEM_BYTES (2 * STAGEB)

__global__ __launch_bounds__(512, 1)
void gemm_mma_kernel(const float* __restrict__ A, const float* __restrict__ Apos,
                     const __nv_bfloat16* __restrict__ Bhi,
                     const __nv_bfloat16* __restrict__ Blo,
                     const float* __restrict__ bias, float* __restrict__ C, float scale)
{
    extern __shared__ char sm[];
    const uint32_t sb = smem_u32(sm);

    const int tid = threadIdx.x, lane = tid & 31, wid = tid >> 5;
    const int m0 = blockIdx.y * 128, n0 = blockIdx.x * 128;
    const int wm = (wid & 3) * 32, wn = (wid >> 2) * 32;
    const int grp = lane >> 2, qid = lane & 3;
    // ldmatrix per-lane offset within a 16x16 fragment: rows lane&15, k-half lane>>4
    const int lm_off = (lane & 15) * ROWB + ((lane >> 4) << 4);

    float acc[2][4][4];
#pragma unroll
    for (int t = 0; t < 2; ++t)
#pragma unroll
        for (int u = 0; u < 4; ++u)
#pragma unroll
            for (int v = 0; v < 4; ++v) acc[t][u][v] = 0.f;

    // Producer slot geometry
    const int a_row0 = (tid * 2) >> 3;        // q=0 row
    const int a_c40  = ((tid * 2) & 7) << 2;  // q=0 col (floats)
    const int a_row1 = (tid * 2 + 1) >> 3;
    const int a_c41  = ((tid * 2 + 1) & 7) << 2;
    const int b_row  = tid >> 2;
    const int b_k8   = (tid & 3) * 8;         // bf16 units

    float4 areg[2];
    uint4  bhreg, blreg;

#define LDG_CHUNK(kb)                                                               \
    do {                                                                            \
        areg[0] = *(const float4*)(A + (size_t)(m0 + a_row0) * 1024 + (kb) + a_c40);\
        areg[1] = *(const float4*)(A + (size_t)(m0 + a_row1) * 1024 + (kb) + a_c41);\
        if (Apos) {                                                                 \
            float4 p0 = *(const float4*)(Apos + (size_t)((m0 + a_row0) & (SS - 1)) * 1024 + (kb) + a_c40); \
            float4 p1 = *(const float4*)(Apos + (size_t)((m0 + a_row1) & (SS - 1)) * 1024 + (kb) + a_c41); \
            areg[0].x += p0.x; areg[0].y += p0.y; areg[0].z += p0.z; areg[0].w += p0.w; \
            areg[1].x += p1.x; areg[1].y += p1.y; areg[1].z += p1.z; areg[1].w += p1.w; \
        }                                                                           \
        bhreg = *(const uint4*)(Bhi + (size_t)(n0 + b_row) * 1024 + (kb) + b_k8);   \
        blreg = *(const uint4*)(Blo + (size_t)(n0 + b_row) * 1024 + (kb) + b_k8);   \
    } while (0)

#define STS_CHUNK(st)                                                               \
    do {                                                                            \
        char* base = sm + (st) * STAGEB;                                            \
        _Pragma("unroll")                                                           \
        for (int q = 0; q < 2; ++q) {                                               \
            int row = q ? a_row1 : a_row0;                                          \
            int c4  = q ? a_c41  : a_c40;                                           \
            float4 v = areg[q];                                                     \
            __nv_bfloat16 h0 = __float2bfloat16_rn(v.x);                            \
            __nv_bfloat16 h1 = __float2bfloat16_rn(v.y);                            \
            __nv_bfloat16 h2 = __float2bfloat16_rn(v.z);                            \
            __nv_bfloat16 h3 = __float2bfloat16_rn(v.w);                            \
            uint2 hs, ls;                                                           \
            hs.x = pack2(h0, h1); hs.y = pack2(h2, h3);                             \
            ls.x = pack2(__float2bfloat16_rn(v.x - __bfloat162float(h0)),           \
                         __float2bfloat16_rn(v.y - __bfloat162float(h1)));          \
            ls.y = pack2(__float2bfloat16_rn(v.z - __bfloat162float(h2)),           \
                         __float2bfloat16_rn(v.w - __bfloat162float(h3)));          \
            *(uint2*)(base + AHI_O + row * ROWB + c4 * 2) = hs;                     \
            *(uint2*)(base + ALO_O + row * ROWB + c4 * 2) = ls;                     \
        }                                                                           \
        *(uint4*)(base + BHI_O + b_row * ROWB + b_k8 * 2) = bhreg;                  \
        *(uint4*)(base + BLO_O + b_row * ROWB + b_k8 * 2) = blreg;                  \
    } while (0)

    // Prologue
    LDG_CHUNK(0);
    STS_CHUNK(0);
    __syncthreads();

    for (int c = 0; c < 32; ++c) {
        const int s = c & 1;
        if (c < 31) LDG_CHUNK((c + 1) * 32);

        const uint32_t sbase = sb + s * STAGEB;
#pragma unroll
        for (int ks = 0; ks < 2; ++ks) {
            const uint32_t ko = ks * 32;   // bytes: 16 bf16
            uint32_t ah[2][4], al[2][4], bh[2][4], bl[2][4];
#pragma unroll
            for (int t = 0; t < 2; ++t) {
                uint32_t ra = (wm + t * 16) * ROWB + lm_off + ko;
                ldm4(ah[t], sbase + AHI_O + ra);
                ldm4(al[t], sbase + ALO_O + ra);
            }
#pragma unroll
            for (int p = 0; p < 2; ++p) {
                uint32_t rb = (wn + p * 16) * ROWB + lm_off + ko;
                ldm4(bh[p], sbase + BHI_O + rb);
                ldm4(bl[p], sbase + BLO_O + rb);
            }
#pragma unroll
            for (int t = 0; t < 2; ++t)
#pragma unroll
                for (int p = 0; p < 2; ++p) {
                    mma_bf16(acc[t][p * 2 + 0], ah[t], bh[p][0], bh[p][2]);
                    mma_bf16(acc[t][p * 2 + 1], ah[t], bh[p][1], bh[p][3]);
                    mma_bf16(acc[t][p * 2 + 0], ah[t], bl[p][0], bl[p][2]);
                    mma_bf16(acc[t][p * 2 + 1], ah[t], bl[p][1], bl[p][3]);
                    mma_bf16(acc[t][p * 2 + 0], al[t], bh[p][0], bh[p][2]);
                    mma_bf16(acc[t][p * 2 + 1], al[t], bh[p][1], bh[p][3]);
                }
        }

        if (c < 31) STS_CHUNK((c + 1) & 1);
        __syncthreads();
    }

    // Epilogue: C fragment -> gmem with bias + scale
#pragma unroll
    for (int t = 0; t < 2; ++t) {
        const int r0 = m0 + wm + t * 16 + grp;
#pragma unroll
        for (int u = 0; u < 4; ++u) {
            const int col = n0 + wn + u * 8 + qid * 2;
            const float b0v = bias[col], b1v = bias[col + 1];
            float2 o0, o1;
            o0.x = (acc[t][u][0] + b0v) * scale;
            o0.y = (acc[t][u][1] + b1v) * scale;
            o1.x = (acc[t][u][2] + b0v) * scale;
            o1.y = (acc[t][u][3] + b1v) * scale;
            *(float2*)(C + (size_t)r0 * 1024 + col) = o0;
            *(float2*)(C + (size_t)(r0 + 8) * 1024 + col) = o1;
        }
    }
#undef LDG_CHUNK
#undef STS_CHUNK
}

// ---------------------------------------------------------------------------
// Flash-style fp32 attention (unchanged from R1)
// ---------------------------------------------------------------------------
#define ATTN_SMEM_FLOATS (128 * 64 + 64 * 65 + 64 * 65 + 128 * 65)
#define ATTN_SMEM_BYTES  (ATTN_SMEM_FLOATS * 4)

__global__ __launch_bounds__(256)
void attn_kernel(const float* __restrict__ ab, const float* __restrict__ abkv)
{
    extern __shared__ float smf[];
    float* Qs = smf;
    float* Ks = Qs + 128 * 64;
    float* Vs = Ks + 64 * 65;
    float* Ps = Vs + 64 * 65;

    const int tid = threadIdx.x;
    const int tx = tid & 15;
    const int ty = tid >> 4;
    const int b  = blockIdx.z;
    const int h  = blockIdx.y;
    const int q0 = blockIdx.x * 128;
    const int r0 = ty * 8;
    const int c0 = tx * 4;

    {
        const size_t baseQ = ((size_t)(b * SS + q0)) * DD + h * HDIM;
#pragma unroll
        for (int it = 0; it < 8; ++it) {
            int slot = tid * 8 + it;
            int row  = slot >> 4;
            int c4   = (slot & 15) << 2;
            *(float4*)&Qs[row * 64 + c4] =
                *(const float4*)(g_Q + baseQ + (size_t)row * DD + c4);
        }
    }

    float acc[8][4];
#pragma unroll
    for (int i = 0; i < 8; ++i)
#pragma unroll
        for (int j = 0; j < 4; ++j) acc[i][j] = 0.f;
    float mrow[8], lrow[8];
#pragma unroll
    for (int i = 0; i < 8; ++i) { mrow[i] = -1e30f; lrow[i] = 0.f; }

    for (int kt = 0; kt < 32; ++kt) {
        const int k0 = kt * 64;
#pragma unroll
        for (int it = 0; it < 4; ++it) {
            int slot = tid * 4 + it;
            int row  = slot >> 4;
            int c4   = (slot & 15) << 2;
            size_t g = ((size_t)(b * SS + k0 + row)) * DD + h * HDIM + c4;
            float4 kv = *(const float4*)(g_K + g);
            Ks[row * 65 + c4 + 0] = kv.x;
            Ks[row * 65 + c4 + 1] = kv.y;
            Ks[row * 65 + c4 + 2] = kv.z;
            Ks[row * 65 + c4 + 3] = kv.w;
            float4 vv = *(const float4*)(g_V + g);
            Vs[row * 65 + c4 + 0] = vv.x;
            Vs[row * 65 + c4 + 1] = vv.y;
            Vs[row * 65 + c4 + 2] = vv.z;
            Vs[row * 65 + c4 + 3] = vv.w;
        }
        __syncthreads();

        float sacc[8][4];
#pragma unroll
        for (int i = 0; i < 8; ++i)
#pragma unroll
            for (int j = 0; j < 4; ++j) sacc[i][j] = 0.f;

#pragma unroll 4
        for (int k = 0; k < 64; ++k) {
            float qf[8], kf[4];
#pragma unroll
            for (int i = 0; i < 8; ++i) qf[i] = Qs[(r0 + i) * 64 + k];
#pragma unroll
            for (int j = 0; j < 4; ++j) kf[j] = Ks[(c0 + j) * 65 + k];
#pragma unroll
            for (int i = 0; i < 8; ++i)
#pragma unroll
                for (int j = 0; j < 4; ++j)
                    sacc[i][j] += qf[i] * kf[j];
        }

#pragma unroll
        for (int i = 0; i < 8; ++i) {
            const int r = r0 + i;
            float mx = -1e30f;
#pragma unroll
            for (int j = 0; j < 4; ++j) {
                float sv = sacc[i][j]
                         + ab[(size_t)(q0 + r) * SS + k0 + c0 + j]
                         + abkv[b * SS + k0 + c0 + j];
                sacc[i][j] = sv;
                mx = fmaxf(mx, sv);
            }
#pragma unroll
            for (int off = 8; off; off >>= 1)
                mx = fmaxf(mx, __shfl_xor_sync(0xffffffffu, mx, off));
            float mnew = fmaxf(mrow[i], mx);
            float f = __expf(mrow[i] - mnew);
            float rs = 0.f;
#pragma unroll
            for (int j = 0; j < 4; ++j) {
                float p = __expf(sacc[i][j] - mnew);
                rs += p;
                Ps[(size_t)r * 65 + c0 + j] = p;
            }
#pragma unroll
            for (int off = 8; off; off >>= 1)
                rs += __shfl_xor_sync(0xffffffffu, rs, off);
            lrow[i] = lrow[i] * f + rs;
            mrow[i] = mnew;
#pragma unroll
            for (int j = 0; j < 4; ++j) acc[i][j] *= f;
        }
        __syncthreads();

#pragma unroll 4
        for (int c = 0; c < 64; ++c) {
            float pf[8], vf[4];
#pragma unroll
            for (int i = 0; i < 8; ++i) pf[i] = Ps[(r0 + i) * 65 + c];
#pragma unroll
            for (int j = 0; j < 4; ++j) vf[j] = Vs[c * 65 + c0 + j];
#pragma unroll
            for (int i = 0; i < 8; ++i)
#pragma unroll
                for (int j = 0; j < 4; ++j)
                    acc[i][j] += pf[i] * vf[j];
        }
        __syncthreads();
    }

#pragma unroll
    for (int i = 0; i < 8; ++i) {
        float inv = 1.f / lrow[i];
        int r = q0 + r0 + i;
        size_t base = ((size_t)(b * SS + r)) * DD + h * HDIM + c0;
#pragma unroll
        for (int j = 0; j < 4; ++j)
            g_X[base + j] = acc[i][j] * inv;
    }
}

// ---------------------------------------------------------------------------
extern "C" void kernel_launch(void* const* d_in, const int* in_sizes, int n_in,
                              void* d_out, int out_size)
{
    const float* x    = (const float*)d_in[0];
    const float* pq   = (const float*)d_in[1];
    const float* pk   = (const float*)d_in[2];
    const float* pv   = (const float*)d_in[3];
    const float* ab   = (const float*)d_in[4];
    const float* abkv = (const float*)d_in[5];
    const float* wq   = (const float*)d_in[6];
    const float* bq   = (const float*)d_in[7];
    const float* wk   = (const float*)d_in[8];
    const float* bk   = (const float*)d_in[9];
    const float* wv   = (const float*)d_in[10];
    const float* bv   = (const float*)d_in[11];
    const float* wo   = (const float*)d_in[12];
    const float* bo   = (const float*)d_in[13];
    float* out = (float*)d_out;

    float *Qp, *Kp, *Vp, *Xp;
    __nv_bfloat16 *Whi, *Wlo;
    cudaGetSymbolAddress((void**)&Qp, g_Q);
    cudaGetSymbolAddress((void**)&Kp, g_K);
    cudaGetSymbolAddress((void**)&Vp, g_V);
    cudaGetSymbolAddress((void**)&Xp, g_X);
    cudaGetSymbolAddress((void**)&Whi, g_Whi);
    cudaGetSymbolAddress((void**)&Wlo, g_Wlo);
    const size_t WSZ = (size_t)1024 * 1024;

    // Prep: transpose + bf16-split all four weight matrices
    dim3 pgrid(32, 32), pblk(32, 8);
    prep_w_kernel<<<pgrid, pblk>>>(wq, Whi + 0 * WSZ, Wlo + 0 * WSZ);
    prep_w_kernel<<<pgrid, pblk>>>(wk, Whi + 1 * WSZ, Wlo + 1 * WSZ);
    prep_w_kernel<<<pgrid, pblk>>>(wv, Whi + 2 * WSZ, Wlo + 2 * WSZ);
    prep_w_kernel<<<pgrid, pblk>>>(wo, Whi + 3 * WSZ, Wlo + 3 * WSZ);

    cudaFuncSetAttribute(gemm_mma_kernel, cudaFuncAttributeMaxDynamicSharedMemorySize,
                         GEMM_SMEM_BYTES);
    dim3 ggrid(1024 / 128, 8192 / 128);   // (8, 64)

    gemm_mma_kernel<<<ggrid, 512, GEMM_SMEM_BYTES>>>(x, pq, Whi + 0 * WSZ, Wlo + 0 * WSZ, bq, Qp, 0.125f);
    gemm_mma_kernel<<<ggrid, 512, GEMM_SMEM_BYTES>>>(x, pk, Whi + 1 * WSZ, Wlo + 1 * WSZ, bk, Kp, 1.0f);
    gemm_mma_kernel<<<ggrid, 512, GEMM_SMEM_BYTES>>>(x, pv, Whi + 2 * WSZ, Wlo + 2 * WSZ, bv, Vp, 1.0f);

    cudaFuncSetAttribute(attn_kernel, cudaFuncAttributeMaxDynamicSharedMemorySize,
                         ATTN_SMEM_BYTES);
    attn_kernel<<<dim3(SS / 128, HH, BB), 256, ATTN_SMEM_BYTES>>>(ab, abkv);

    gemm_mma_kernel<<<ggrid, 512, GEMM_SMEM_BYTES>>>(Xp, nullptr, Whi + 3 * WSZ, Wlo + 3 * WSZ, bo, out, 1.0f);
}

// round 4
// speedup vs baseline: 2.1237x; 1.6742x over previous
#include <cuda_runtime.h>
#include <cuda_bf16.h>
#include <cstdint>
#include <math.h>

// Problem constants
#define BB   4
#define SS   2048
#define DD   1024
#define HH   16
#define HDIM 64

// Scratch (allocation-free rule: __device__ globals)
__device__ float g_X[(size_t)8192 * 1024];
// bf16-split activations (written by projection GEMM epilogues)
__device__ __nv_bfloat16 g_Qhi[(size_t)8192 * 1024];
__device__ __nv_bfloat16 g_Qlo[(size_t)8192 * 1024];
__device__ __nv_bfloat16 g_Khi[(size_t)8192 * 1024];
__device__ __nv_bfloat16 g_Klo[(size_t)8192 * 1024];
__device__ __nv_bfloat16 g_Vhi[(size_t)8192 * 1024];
__device__ __nv_bfloat16 g_Vlo[(size_t)8192 * 1024];
// Pre-transposed + bf16-split weights: [4][N=1024][K=1024]
__device__ __nv_bfloat16 g_Whi[4][(size_t)1024 * 1024];
__device__ __nv_bfloat16 g_Wlo[4][(size_t)1024 * 1024];

// ---------------------------------------------------------------------------
// Helpers
// ---------------------------------------------------------------------------
__device__ __forceinline__ uint32_t smem_u32(const void* p) {
    uint32_t a;
    asm("{ .reg .u64 t; cvta.to.shared.u64 t, %1; cvt.u32.u64 %0, t; }" : "=r"(a) : "l"(p));
    return a;
}
__device__ __forceinline__ void ldm4(uint32_t* r, uint32_t addr) {
    asm volatile("ldmatrix.sync.aligned.m8n8.x4.shared.b16 {%0,%1,%2,%3}, [%4];"
                 : "=r"(r[0]), "=r"(r[1]), "=r"(r[2]), "=r"(r[3]) : "r"(addr));
}
__device__ __forceinline__ void ldm4t(uint32_t* r, uint32_t addr) {
    asm volatile("ldmatrix.sync.aligned.m8n8.x4.trans.shared.b16 {%0,%1,%2,%3}, [%4];"
                 : "=r"(r[0]), "=r"(r[1]), "=r"(r[2]), "=r"(r[3]) : "r"(addr));
}
__device__ __forceinline__ void mma_bf16(float* c, const uint32_t* a, uint32_t b0, uint32_t b1) {
    asm volatile(
        "mma.sync.aligned.m16n8k16.row.col.f32.bf16.bf16.f32 "
        "{%0,%1,%2,%3}, {%4,%5,%6,%7}, {%8,%9}, {%0,%1,%2,%3};"
        : "+f"(c[0]), "+f"(c[1]), "+f"(c[2]), "+f"(c[3])
        : "r"(a[0]), "r"(a[1]), "r"(a[2]), "r"(a[3]), "r"(b0), "r"(b1));
}
__device__ __forceinline__ uint32_t pack2(__nv_bfloat16 a, __nv_bfloat16 b) {
    __nv_bfloat162 t = __halves2bfloat162(a, b);
    return *(uint32_t*)&t;
}
__device__ __forceinline__ void cp16(uint32_t dst, const void* src) {
    asm volatile("cp.async.cg.shared.global [%0], [%1], 16;" :: "r"(dst), "l"(src));
}
#define CP_COMMIT() asm volatile("cp.async.commit_group;" ::: "memory")
#define CP_WAIT(N)  asm volatile("cp.async.wait_group %0;" :: "n"(N) : "memory")

// ---------------------------------------------------------------------------
// Prep: transpose W[K=1024][N=1024] -> [N][K], split into bf16 hi/lo
// ---------------------------------------------------------------------------
__global__ void prep_w_kernel(const float* __restrict__ W,
                              __nv_bfloat16* __restrict__ Whi,
                              __nv_bfloat16* __restrict__ Wlo)
{
    __shared__ float t[32][33];
    const int n0 = blockIdx.x * 32, k0 = blockIdx.y * 32;
    const int tx = threadIdx.x, ty = threadIdx.y;
#pragma unroll
    for (int i = 0; i < 4; ++i)
        t[ty + i * 8][tx] = W[(size_t)(k0 + ty + i * 8) * 1024 + n0 + tx];
    __syncthreads();
#pragma unroll
    for (int i = 0; i < 4; ++i) {
        int n = n0 + ty + i * 8;
        float x = t[tx][ty + i * 8];
        __nv_bfloat16 h = __float2bfloat16_rn(x);
        Whi[(size_t)n * 1024 + k0 + tx] = h;
        Wlo[(size_t)n * 1024 + k0 + tx] = __float2bfloat16_rn(x - __bfloat162float(h));
    }
}

// ---------------------------------------------------------------------------
// mma.sync bf16-split GEMM: C = ((A[+Apos]) @ W + bias) * scale
// If Chi != null: write bf16 hi/lo split outputs instead of fp32 C.
// ---------------------------------------------------------------------------
#define ROWB   80
#define AHI_O  0
#define ALO_O  10240
#define BHI_O  20480
#define BLO_O  30720
#define STAGEB 40960
#define GEMM_SMEM_BYTES (2 * STAGEB)

__global__ __launch_bounds__(512, 1)
void gemm_mma_kernel(const float* __restrict__ A, const float* __restrict__ Apos,
                     const __nv_bfloat16* __restrict__ Bhi,
                     const __nv_bfloat16* __restrict__ Blo,
                     const float* __restrict__ bias, float* __restrict__ C,
                     __nv_bfloat16* __restrict__ Chi, __nv_bfloat16* __restrict__ Clo,
                     float scale)
{
    extern __shared__ char sm[];
    const uint32_t sb = smem_u32(sm);

    const int tid = threadIdx.x, lane = tid & 31, wid = tid >> 5;
    const int m0 = blockIdx.y * 128, n0 = blockIdx.x * 128;
    const int wm = (wid & 3) * 32, wn = (wid >> 2) * 32;
    const int grp = lane >> 2, qid = lane & 3;
    const int lm_off = (lane & 15) * ROWB + ((lane >> 4) << 4);

    float acc[2][4][4];
#pragma unroll
    for (int t = 0; t < 2; ++t)
#pragma unroll
        for (int u = 0; u < 4; ++u)
#pragma unroll
            for (int v = 0; v < 4; ++v) acc[t][u][v] = 0.f;

    const int a_row0 = (tid * 2) >> 3;
    const int a_c40  = ((tid * 2) & 7) << 2;
    const int a_row1 = (tid * 2 + 1) >> 3;
    const int a_c41  = ((tid * 2 + 1) & 7) << 2;
    const int b_row  = tid >> 2;
    const int b_k8   = (tid & 3) * 8;

    float4 areg[2];
    uint4  bhreg, blreg;

#define LDG_CHUNK(kb)                                                               \
    do {                                                                            \
        areg[0] = *(const float4*)(A + (size_t)(m0 + a_row0) * 1024 + (kb) + a_c40);\
        areg[1] = *(const float4*)(A + (size_t)(m0 + a_row1) * 1024 + (kb) + a_c41);\
        if (Apos) {                                                                 \
            float4 p0 = *(const float4*)(Apos + (size_t)((m0 + a_row0) & (SS - 1)) * 1024 + (kb) + a_c40); \
            float4 p1 = *(const float4*)(Apos + (size_t)((m0 + a_row1) & (SS - 1)) * 1024 + (kb) + a_c41); \
            areg[0].x += p0.x; areg[0].y += p0.y; areg[0].z += p0.z; areg[0].w += p0.w; \
            areg[1].x += p1.x; areg[1].y += p1.y; areg[1].z += p1.z; areg[1].w += p1.w; \
        }                                                                           \
        bhreg = *(const uint4*)(Bhi + (size_t)(n0 + b_row) * 1024 + (kb) + b_k8);   \
        blreg = *(const uint4*)(Blo + (size_t)(n0 + b_row) * 1024 + (kb) + b_k8);   \
    } while (0)

#define STS_CHUNK(st)                                                               \
    do {                                                                            \
        char* base = sm + (st) * STAGEB;                                            \
        _Pragma("unroll")                                                           \
        for (int q = 0; q < 2; ++q) {                                               \
            int row = q ? a_row1 : a_row0;                                          \
            int c4  = q ? a_c41  : a_c40;                                           \
            float4 v = areg[q];                                                     \
            __nv_bfloat16 h0 = __float2bfloat16_rn(v.x);                            \
            __nv_bfloat16 h1 = __float2bfloat16_rn(v.y);                            \
            __nv_bfloat16 h2 = __float2bfloat16_rn(v.z);                            \
            __nv_bfloat16 h3 = __float2bfloat16_rn(v.w);                            \
            uint2 hs, ls;                                                           \
            hs.x = pack2(h0, h1); hs.y = pack2(h2, h3);                             \
            ls.x = pack2(__float2bfloat16_rn(v.x - __bfloat162float(h0)),           \
                         __float2bfloat16_rn(v.y - __bfloat162float(h1)));          \
            ls.y = pack2(__float2bfloat16_rn(v.z - __bfloat162float(h2)),           \
                         __float2bfloat16_rn(v.w - __bfloat162float(h3)));          \
            *(uint2*)(base + AHI_O + row * ROWB + c4 * 2) = hs;                     \
            *(uint2*)(base + ALO_O + row * ROWB + c4 * 2) = ls;                     \
        }                                                                           \
        *(uint4*)(base + BHI_O + b_row * ROWB + b_k8 * 2) = bhreg;                  \
        *(uint4*)(base + BLO_O + b_row * ROWB + b_k8 * 2) = blreg;                  \
    } while (0)

    LDG_CHUNK(0);
    STS_CHUNK(0);
    __syncthreads();

    for (int c = 0; c < 32; ++c) {
        const int s = c & 1;
        if (c < 31) LDG_CHUNK((c + 1) * 32);

        const uint32_t sbase = sb + s * STAGEB;
#pragma unroll
        for (int ks = 0; ks < 2; ++ks) {
            const uint32_t ko = ks * 32;
            uint32_t ah[2][4], al[2][4], bh[2][4], bl[2][4];
#pragma unroll
            for (int t = 0; t < 2; ++t) {
                uint32_t ra = (wm + t * 16) * ROWB + lm_off + ko;
                ldm4(ah[t], sbase + AHI_O + ra);
                ldm4(al[t], sbase + ALO_O + ra);
            }
#pragma unroll
            for (int p = 0; p < 2; ++p) {
                uint32_t rb = (wn + p * 16) * ROWB + lm_off + ko;
                ldm4(bh[p], sbase + BHI_O + rb);
                ldm4(bl[p], sbase + BLO_O + rb);
            }
#pragma unroll
            for (int t = 0; t < 2; ++t)
#pragma unroll
                for (int p = 0; p < 2; ++p) {
                    mma_bf16(acc[t][p * 2 + 0], ah[t], bh[p][0], bh[p][2]);
                    mma_bf16(acc[t][p * 2 + 1], ah[t], bh[p][1], bh[p][3]);
                    mma_bf16(acc[t][p * 2 + 0], ah[t], bl[p][0], bl[p][2]);
                    mma_bf16(acc[t][p * 2 + 1], ah[t], bl[p][1], bl[p][3]);
                    mma_bf16(acc[t][p * 2 + 0], al[t], bh[p][0], bh[p][2]);
                    mma_bf16(acc[t][p * 2 + 1], al[t], bh[p][1], bh[p][3]);
                }
        }

        if (c < 31) STS_CHUNK((c + 1) & 1);
        __syncthreads();
    }

    // Epilogue
#pragma unroll
    for (int t = 0; t < 2; ++t) {
        const int r0 = m0 + wm + t * 16 + grp;
#pragma unroll
        for (int u = 0; u < 4; ++u) {
            const int col = n0 + wn + u * 8 + qid * 2;
            const float b0v = bias[col], b1v = bias[col + 1];
            float v00 = (acc[t][u][0] + b0v) * scale;
            float v01 = (acc[t][u][1] + b1v) * scale;
            float v10 = (acc[t][u][2] + b0v) * scale;
            float v11 = (acc[t][u][3] + b1v) * scale;
            if (Chi) {
                __nv_bfloat16 h00 = __float2bfloat16_rn(v00);
                __nv_bfloat16 h01 = __float2bfloat16_rn(v01);
                __nv_bfloat16 h10 = __float2bfloat16_rn(v10);
                __nv_bfloat16 h11 = __float2bfloat16_rn(v11);
                *(uint32_t*)(Chi + (size_t)r0 * 1024 + col) = pack2(h00, h01);
                *(uint32_t*)(Chi + (size_t)(r0 + 8) * 1024 + col) = pack2(h10, h11);
                *(uint32_t*)(Clo + (size_t)r0 * 1024 + col) =
                    pack2(__float2bfloat16_rn(v00 - __bfloat162float(h00)),
                          __float2bfloat16_rn(v01 - __bfloat162float(h01)));
                *(uint32_t*)(Clo + (size_t)(r0 + 8) * 1024 + col) =
                    pack2(__float2bfloat16_rn(v10 - __bfloat162float(h10)),
                          __float2bfloat16_rn(v11 - __bfloat162float(h11)));
            } else {
                float2 o0 = {v00, v01}, o1 = {v10, v11};
                *(float2*)(C + (size_t)r0 * 1024 + col) = o0;
                *(float2*)(C + (size_t)(r0 + 8) * 1024 + col) = o1;
            }
        }
    }
#undef LDG_CHUNK
#undef STS_CHUNK
}

// ---------------------------------------------------------------------------
// Flash attention, mma.sync bf16-split, register-resident P.
// 256 threads = 8 warps; warp w owns rows 16w..16w+15 of a 128-row q-tile.
// K-tiles of 64 keys, double-buffered via cp.async.
// ---------------------------------------------------------------------------
#define AROWB  144                      // 64 bf16 (128B) + 16B pad
#define A_QHI  0
#define A_QLO  18432
#define A_ST0  36864
#define A_STB  36864                    // bytes per stage (4 tiles x 64 x 144)
#define A_KHI  0
#define A_KLO  9216
#define A_VHI  18432
#define A_VLO  27648
#define ATTN_SMEM_BYTES (A_ST0 + 2 * A_STB)

__global__ __launch_bounds__(256, 1)
void attn_mma_kernel(const float* __restrict__ ab, const float* __restrict__ abkv)
{
    extern __shared__ char sm[];
    const uint32_t sb = smem_u32(sm);
    const int tid = threadIdx.x, lane = tid & 31, wid = tid >> 5;
    const int grp = lane >> 2, qid = lane & 3;
    const int b = blockIdx.z, h = blockIdx.y, q0 = blockIdx.x * 128;
    const int wr = wid * 16;
    const int lm_off = (lane & 15) * AROWB + ((lane >> 4) << 4);

    // ---- async Q load (hi+lo) into staging ----
    {
#pragma unroll
        for (int i = 0; i < 8; ++i) {
            int idx = i * 256 + tid;            // 0..2047
            int arr = idx >> 10;                // 0=hi 1=lo
            int rem = idx & 1023;
            int row = rem >> 3, ch = rem & 7;
            const __nv_bfloat16* g = (arr ? g_Qlo : g_Qhi)
                + (size_t)(b * SS + q0 + row) * 1024 + h * 64 + ch * 8;
            cp16(sb + (arr ? A_QLO : A_QHI) + row * AROWB + ch * 16, g);
        }
    }

    // tile issuer
    auto issue_tile = [&](int kt) {
        const uint32_t st = sb + A_ST0 + (kt & 1) * A_STB;
        const int k0 = kt * 64;
#pragma unroll
        for (int i = 0; i < 8; ++i) {
            int idx = i * 256 + tid;            // 0..2047
            int arr = idx >> 9;                 // 0..3: Khi,Klo,Vhi,Vlo
            int rem = idx & 511;
            int row = rem >> 3, ch = rem & 7;
            const __nv_bfloat16* gb =
                (arr == 0 ? g_Khi : arr == 1 ? g_Klo : arr == 2 ? g_Vhi : g_Vlo)
                + (size_t)(b * SS + k0 + row) * 1024 + h * 64 + ch * 8;
            uint32_t so = (arr == 0 ? A_KHI : arr == 1 ? A_KLO : arr == 2 ? A_VHI : A_VLO);
            cp16(st + so + row * AROWB + ch * 16, gb);
        }
    };

    issue_tile(0);
    CP_COMMIT();            // G0 = Q + tile0
    issue_tile(1);
    CP_COMMIT();            // G1 = tile1
    CP_WAIT(1);             // Q + tile0 ready
    __syncthreads();

    // ---- Q fragments to registers ----
    uint32_t qhi[4][4], qlo[4][4];
#pragma unroll
    for (int ks = 0; ks < 4; ++ks) {
        uint32_t ra = wr * AROWB + lm_off + ks * 32;
        ldm4(qhi[ks], sb + A_QHI + ra);
        ldm4(qlo[ks], sb + A_QLO + ra);
    }

    float oacc[8][4];
#pragma unroll
    for (int f = 0; f < 8; ++f)
#pragma unroll
        for (int v = 0; v < 4; ++v) oacc[f][v] = 0.f;
    float m0 = -1e30f, m1 = -1e30f, l0 = 0.f, l1 = 0.f;

    const float* abp   = ab + (size_t)(q0 + wr + grp) * SS + qid * 2;
    const float* abkvp = abkv + b * SS + qid * 2;

    for (int kt = 0; kt < 32; ++kt) {
        const uint32_t st = sb + A_ST0 + (kt & 1) * A_STB;
        const int k0 = kt * 64;

        if (kt < 31) { CP_WAIT(1); } else { CP_WAIT(0); }
        __syncthreads();

        // ---- S = Q K^T (3-term split) ----
        float sacc[8][4];
#pragma unroll
        for (int f = 0; f < 8; ++f)
#pragma unroll
            for (int v = 0; v < 4; ++v) sacc[f][v] = 0.f;

#pragma unroll
        for (int ks = 0; ks < 4; ++ks) {
            uint32_t kh[4][4], kl[4][4];
#pragma unroll
            for (int j = 0; j < 4; ++j) {
                uint32_t rb = (j * 16) * AROWB + lm_off + ks * 32;
                ldm4(kh[j], st + A_KHI + rb);
                ldm4(kl[j], st + A_KLO + rb);
            }
#pragma unroll
            for (int j = 0; j < 4; ++j) {
                mma_bf16(sacc[2 * j + 0], qhi[ks], kh[j][0], kh[j][2]);
                mma_bf16(sacc[2 * j + 1], qhi[ks], kh[j][1], kh[j][3]);
                mma_bf16(sacc[2 * j + 0], qhi[ks], kl[j][0], kl[j][2]);
                mma_bf16(sacc[2 * j + 1], qhi[ks], kl[j][1], kl[j][3]);
                mma_bf16(sacc[2 * j + 0], qlo[ks], kh[j][0], kh[j][2]);
                mma_bf16(sacc[2 * j + 1], qlo[ks], kh[j][1], kh[j][3]);
            }
        }

        // ---- bias + online softmax ----
        float mx0 = -1e30f, mx1 = -1e30f;
#pragma unroll
        for (int f = 0; f < 8; ++f) {
            float2 bk = *(const float2*)(abkvp + k0 + f * 8);
            float2 b0 = *(const float2*)(abp + k0 + f * 8);
            float2 b1 = *(const float2*)(abp + 8 * SS + k0 + f * 8);
            sacc[f][0] += b0.x + bk.x; sacc[f][1] += b0.y + bk.y;
            sacc[f][2] += b1.x + bk.x; sacc[f][3] += b1.y + bk.y;
            mx0 = fmaxf(mx0, fmaxf(sacc[f][0], sacc[f][1]));
            mx1 = fmaxf(mx1, fmaxf(sacc[f][2], sacc[f][3]));
        }
        mx0 = fmaxf(mx0, __shfl_xor_sync(0xffffffffu, mx0, 1));
        mx0 = fmaxf(mx0, __shfl_xor_sync(0xffffffffu, mx0, 2));
        mx1 = fmaxf(mx1, __shfl_xor_sync(0xffffffffu, mx1, 1));
        mx1 = fmaxf(mx1, __shfl_xor_sync(0xffffffffu, mx1, 2));

        const float mn0 = fmaxf(m0, mx0), mn1 = fmaxf(m1, mx1);
        const float e0 = __expf(m0 - mn0), e1 = __expf(m1 - mn1);
        m0 = mn0; m1 = mn1;

        float rs0 = 0.f, rs1 = 0.f;
        uint32_t aPhi[4][4], aPlo[4][4];
#pragma unroll
        for (int j = 0; j < 4; ++j) {
            float p[8];
            p[0] = __expf(sacc[2 * j][0] - mn0);
            p[1] = __expf(sacc[2 * j][1] - mn0);
            p[2] = __expf(sacc[2 * j][2] - mn1);
            p[3] = __expf(sacc[2 * j][3] - mn1);
            p[4] = __expf(sacc[2 * j + 1][0] - mn0);
            p[5] = __expf(sacc[2 * j + 1][1] - mn0);
            p[6] = __expf(sacc[2 * j + 1][2] - mn1);
            p[7] = __expf(sacc[2 * j + 1][3] - mn1);
            rs0 += p[0] + p[1] + p[4] + p[5];
            rs1 += p[2] + p[3] + p[6] + p[7];
            __nv_bfloat16 hh[8];
#pragma unroll
            for (int t = 0; t < 8; ++t) hh[t] = __float2bfloat16_rn(p[t]);
            aPhi[j][0] = pack2(hh[0], hh[1]);
            aPhi[j][1] = pack2(hh[2], hh[3]);
            aPhi[j][2] = pack2(hh[4], hh[5]);
            aPhi[j][3] = pack2(hh[6], hh[7]);
            aPlo[j][0] = pack2(__float2bfloat16_rn(p[0] - __bfloat162float(hh[0])),
                               __float2bfloat16_rn(p[1] - __bfloat162float(hh[1])));
            aPlo[j][1] = pack2(__float2bfloat16_rn(p[2] - __bfloat162float(hh[2])),
                               __float2bfloat16_rn(p[3] - __bfloat162float(hh[3])));
            aPlo[j][2] = pack2(__float2bfloat16_rn(p[4] - __bfloat162float(hh[4])),
                               __float2bfloat16_rn(p[5] - __bfloat162float(hh[5])));
            aPlo[j][3] = pack2(__float2bfloat16_rn(p[6] - __bfloat162float(hh[6])),
                               __float2bfloat16_rn(p[7] - __bfloat162float(hh[7])));
        }
        l0 = l0 * e0 + rs0;
        l1 = l1 * e1 + rs1;
#pragma unroll
        for (int f = 0; f < 8; ++f) {
            oacc[f][0] *= e0; oacc[f][1] *= e0;
            oacc[f][2] *= e1; oacc[f][3] *= e1;
        }

        // ---- O += P V (3-term split, P in registers) ----
#pragma unroll
        for (int j = 0; j < 4; ++j) {
            uint32_t vh[4][4], vl[4][4];
#pragma unroll
            for (int jj = 0; jj < 4; ++jj) {
                uint32_t rb = (j * 16) * AROWB + (lane & 15) * AROWB + jj * 32 + ((lane >> 4) << 4);
                ldm4t(vh[jj], st + A_VHI + rb);
                ldm4t(vl[jj], st + A_VLO + rb);
            }
#pragma unroll
            for (int jj = 0; jj < 4; ++jj) {
                mma_bf16(oacc[2 * jj + 0], aPhi[j], vh[jj][0], vh[jj][1]);
                mma_bf16(oacc[2 * jj + 1], aPhi[j], vh[jj][2], vh[jj][3]);
                mma_bf16(oacc[2 * jj + 0], aPhi[j], vl[jj][0], vl[jj][1]);
                mma_bf16(oacc[2 * jj + 1], aPhi[j], vl[jj][2], vl[jj][3]);
                mma_bf16(oacc[2 * jj + 0], aPlo[j], vh[jj][0], vh[jj][1]);
                mma_bf16(oacc[2 * jj + 1], aPlo[j], vh[jj][2], vh[jj][3]);
            }
        }

        __syncthreads();          // everyone done reading this stage
        if (kt + 2 < 32) { issue_tile(kt + 2); CP_COMMIT(); }
    }

    // ---- normalize + write ----
    l0 += __shfl_xor_sync(0xffffffffu, l0, 1);
    l0 += __shfl_xor_sync(0xffffffffu, l0, 2);
    l1 += __shfl_xor_sync(0xffffffffu, l1, 1);
    l1 += __shfl_xor_sync(0xffffffffu, l1, 2);
    const float inv0 = 1.f / l0, inv1 = 1.f / l1;

    float* Xp = g_X + (size_t)(b * SS + q0 + wr + grp) * 1024 + h * 64 + qid * 2;
#pragma unroll
    for (int f = 0; f < 8; ++f) {
        float2 o0 = {oacc[f][0] * inv0, oacc[f][1] * inv0};
        float2 o1 = {oacc[f][2] * inv1, oacc[f][3] * inv1};
        *(float2*)(Xp + f * 8) = o0;
        *(float2*)(Xp + (size_t)8 * 1024 + f * 8) = o1;
    }
}

// ---------------------------------------------------------------------------
extern "C" void kernel_launch(void* const* d_in, const int* in_sizes, int n_in,
                              void* d_out, int out_size)
{
    const float* x    = (const float*)d_in[0];
    const float* pq   = (const float*)d_in[1];
    const float* pk   = (const float*)d_in[2];
    const float* pv   = (const float*)d_in[3];
    const float* ab   = (const float*)d_in[4];
    const float* abkv = (const float*)d_in[5];
    const float* wq   = (const float*)d_in[6];
    const float* bq   = (const float*)d_in[7];
    const float* wk   = (const float*)d_in[8];
    const float* bk   = (const float*)d_in[9];
    const float* wv   = (const float*)d_in[10];
    const float* bv   = (const float*)d_in[11];
    const float* wo   = (const float*)d_in[12];
    const float* bo   = (const float*)d_in[13];
    float* out = (float*)d_out;

    float *Xp;
    __nv_bfloat16 *Whi, *Wlo, *Qhi, *Qlo, *Khi, *Klo, *Vhi, *Vlo;
    cudaGetSymbolAddress((void**)&Xp, g_X);
    cudaGetSymbolAddress((void**)&Whi, g_Whi);
    cudaGetSymbolAddress((void**)&Wlo, g_Wlo);
    cudaGetSymbolAddress((void**)&Qhi, g_Qhi);
    cudaGetSymbolAddress((void**)&Qlo, g_Qlo);
    cudaGetSymbolAddress((void**)&Khi, g_Khi);
    cudaGetSymbolAddress((void**)&Klo, g_Klo);
    cudaGetSymbolAddress((void**)&Vhi, g_Vhi);
    cudaGetSymbolAddress((void**)&Vlo, g_Vlo);
    const size_t WSZ = (size_t)1024 * 1024;

    dim3 pgrid(32, 32), pblk(32, 8);
    prep_w_kernel<<<pgrid, pblk>>>(wq, Whi + 0 * WSZ, Wlo + 0 * WSZ);
    prep_w_kernel<<<pgrid, pblk>>>(wk, Whi + 1 * WSZ, Wlo + 1 * WSZ);
    prep_w_kernel<<<pgrid, pblk>>>(wv, Whi + 2 * WSZ, Wlo + 2 * WSZ);
    prep_w_kernel<<<pgrid, pblk>>>(wo, Whi + 3 * WSZ, Wlo + 3 * WSZ);

    cudaFuncSetAttribute(gemm_mma_kernel, cudaFuncAttributeMaxDynamicSharedMemorySize,
                         GEMM_SMEM_BYTES);
    dim3 ggrid(1024 / 128, 8192 / 128);

    gemm_mma_kernel<<<ggrid, 512, GEMM_SMEM_BYTES>>>(x, pq, Whi + 0 * WSZ, Wlo + 0 * WSZ,
                                                     bq, nullptr, Qhi, Qlo, 0.125f);
    gemm_mma_kernel<<<ggrid, 512, GEMM_SMEM_BYTES>>>(x, pk, Whi + 1 * WSZ, Wlo + 1 * WSZ,
                                                     bk, nullptr, Khi, Klo, 1.0f);
    gemm_mma_kernel<<<ggrid, 512, GEMM_SMEM_BYTES>>>(x, pv, Whi + 2 * WSZ, Wlo + 2 * WSZ,
                                                     bv, nullptr, Vhi, Vlo, 1.0f);

    cudaFuncSetAttribute(attn_mma_kernel, cudaFuncAttributeMaxDynamicSharedMemorySize,
                         ATTN_SMEM_BYTES);
    attn_mma_kernel<<<dim3(SS / 128, HH, BB), 256, ATTN_SMEM_BYTES>>>(ab, abkv);

    gemm_mma_kernel<<<ggrid, 512, GEMM_SMEM_BYTES>>>(Xp, nullptr, Whi + 3 * WSZ, Wlo + 3 * WSZ,
                                                     bo, out, nullptr, nullptr, 1.0f);
}

// round 5
// speedup vs baseline: 2.7173x; 1.2795x over previous
#include <cuda_runtime.h>
#include <cuda_fp16.h>
#include <cstdint>
#include <math.h>

// Problem constants
#define BB   4
#define SS   2048
#define DD   1024
#define HH   16
#define HDIM 64

// Scratch (allocation-free rule: __device__ globals)
__device__ __half g_Qh [(size_t)8192 * 1024];      // fp16 single
__device__ __half g_Kh [(size_t)8192 * 1024];      // fp16 single
__device__ __half g_Vhi[(size_t)8192 * 1024];
__device__ __half g_Vlo[(size_t)8192 * 1024];
__device__ __half g_Xhi[(size_t)8192 * 1024];
__device__ __half g_Xlo[(size_t)8192 * 1024];
// Pre-split activations (x + posemb) for q/k/v projections
__device__ __half g_Ahi[3][(size_t)8192 * 1024];
__device__ __half g_Alo[3][(size_t)8192 * 1024];
// Pre-transposed + fp16-split weights: [4][N=1024][K=1024]
__device__ __half g_Whi[4][(size_t)1024 * 1024];
__device__ __half g_Wlo[4][(size_t)1024 * 1024];

// ---------------------------------------------------------------------------
// Helpers
// ---------------------------------------------------------------------------
__device__ __forceinline__ uint32_t smem_u32(const void* p) {
    uint32_t a;
    asm("{ .reg .u64 t; cvta.to.shared.u64 t, %1; cvt.u32.u64 %0, t; }" : "=r"(a) : "l"(p));
    return a;
}
__device__ __forceinline__ void ldm4(uint32_t* r, uint32_t addr) {
    asm volatile("ldmatrix.sync.aligned.m8n8.x4.shared.b16 {%0,%1,%2,%3}, [%4];"
                 : "=r"(r[0]), "=r"(r[1]), "=r"(r[2]), "=r"(r[3]) : "r"(addr));
}
__device__ __forceinline__ void ldm4t(uint32_t* r, uint32_t addr) {
    asm volatile("ldmatrix.sync.aligned.m8n8.x4.trans.shared.b16 {%0,%1,%2,%3}, [%4];"
                 : "=r"(r[0]), "=r"(r[1]), "=r"(r[2]), "=r"(r[3]) : "r"(addr));
}
__device__ __forceinline__ void mma_f16(float* c, const uint32_t* a, uint32_t b0, uint32_t b1) {
    asm volatile(
        "mma.sync.aligned.m16n8k16.row.col.f32.f16.f16.f32 "
        "{%0,%1,%2,%3}, {%4,%5,%6,%7}, {%8,%9}, {%0,%1,%2,%3};"
        : "+f"(c[0]), "+f"(c[1]), "+f"(c[2]), "+f"(c[3])
        : "r"(a[0]), "r"(a[1]), "r"(a[2]), "r"(a[3]), "r"(b0), "r"(b1));
}
__device__ __forceinline__ uint32_t pack2h(__half a, __half b) {
    __half2 t = __halves2half2(a, b);
    return *(uint32_t*)&t;
}
__device__ __forceinline__ void cp16(uint32_t dst, const void* src) {
    asm volatile("cp.async.cg.shared.global [%0], [%1], 16;" :: "r"(dst), "l"(src));
}
#define CP_COMMIT() asm volatile("cp.async.commit_group;" ::: "memory")
#define CP_WAIT(N)  asm volatile("cp.async.wait_group %0;" :: "n"(N) : "memory")

// ---------------------------------------------------------------------------
// Prep 1: transpose W[K][N] -> [N][K], split into fp16 hi/lo
// ---------------------------------------------------------------------------
__global__ void prep_w_kernel(const float* __restrict__ W,
                              __half* __restrict__ Whi, __half* __restrict__ Wlo)
{
    __shared__ float t[32][33];
    const int n0 = blockIdx.x * 32, k0 = blockIdx.y * 32;
    const int tx = threadIdx.x, ty = threadIdx.y;
#pragma unroll
    for (int i = 0; i < 4; ++i)
        t[ty + i * 8][tx] = W[(size_t)(k0 + ty + i * 8) * 1024 + n0 + tx];
    __syncthreads();
#pragma unroll
    for (int i = 0; i < 4; ++i) {
        int n = n0 + ty + i * 8;
        float x = t[tx][ty + i * 8];
        __half h = __float2half_rn(x);
        Whi[(size_t)n * 1024 + k0 + tx] = h;
        Wlo[(size_t)n * 1024 + k0 + tx] = __float2half_rn(x - __half2float(h));
    }
}

// ---------------------------------------------------------------------------
// Prep 2: activations: split(x + pos_{q,k,v}) -> fp16 hi/lo, 3 targets
// ---------------------------------------------------------------------------
__global__ __launch_bounds__(256)
void prep_act_kernel(const float* __restrict__ x, const float* __restrict__ pq,
                     const float* __restrict__ pk, const float* __restrict__ pv)
{
    const size_t base = ((size_t)blockIdx.x * 256 + threadIdx.x) * 4;
    const size_t poff = base & ((size_t)SS * 1024 - 1);
    float4 xv = *(const float4*)(x + base);
    const float* ptab[3] = {pq, pk, pv};
#pragma unroll
    for (int t = 0; t < 3; ++t) {
        float4 pv4 = *(const float4*)(ptab[t] + poff);
        float v[4] = {xv.x + pv4.x, xv.y + pv4.y, xv.z + pv4.z, xv.w + pv4.w};
        __half h[4]; uint32_t hi[2], lo[2];
#pragma unroll
        for (int j = 0; j < 4; ++j) h[j] = __float2half_rn(v[j]);
        hi[0] = pack2h(h[0], h[1]); hi[1] = pack2h(h[2], h[3]);
        lo[0] = pack2h(__float2half_rn(v[0] - __half2float(h[0])),
                       __float2half_rn(v[1] - __half2float(h[1])));
        lo[1] = pack2h(__float2half_rn(v[2] - __half2float(h[2])),
                       __float2half_rn(v[3] - __half2float(h[3])));
        *(uint2*)(&g_Ahi[t][base]) = make_uint2(hi[0], hi[1]);
        *(uint2*)(&g_Alo[t][base]) = make_uint2(lo[0], lo[1]);
    }
}

// ---------------------------------------------------------------------------
// fp16 3-term GEMM, cp.async 4-stage pipeline.
// C = (Ahi+Alo) @ (Whi+Wlo)^T + bias, scaled. Output: fp32 C | fp16 Chi[+Clo].
// ---------------------------------------------------------------------------
#define ROWB   80
#define AHI_O  0
#define ALO_O  10240
#define BHI_O  20480
#define BLO_O  30720
#define STAGEB 40960
#define GEMM_SMEM_BYTES (4 * STAGEB)

__global__ __launch_bounds__(512, 1)
void gemm_mma_kernel(const __half* __restrict__ Ahi, const __half* __restrict__ Alo,
                     const __half* __restrict__ Bhi, const __half* __restrict__ Blo,
                     const float* __restrict__ bias, float* __restrict__ C,
                     __half* __restrict__ Chi, __half* __restrict__ Clo, float scale)
{
    extern __shared__ char sm[];
    const uint32_t sb = smem_u32(sm);

    const int tid = threadIdx.x, lane = tid & 31, wid = tid >> 5;
    const int m0 = blockIdx.y * 128, n0 = blockIdx.x * 128;
    const int wm = (wid & 3) * 32, wn = (wid >> 2) * 32;
    const int grp = lane >> 2, qid = lane & 3;
    const int lm_off = (lane & 15) * ROWB + ((lane >> 4) << 4);
    const int p_row = tid >> 2, p_ch = tid & 3;    // producer: 128 rows x 4 chunks16B

    float acc[2][4][4];
#pragma unroll
    for (int t = 0; t < 2; ++t)
#pragma unroll
        for (int u = 0; u < 4; ++u)
#pragma unroll
            for (int v = 0; v < 4; ++v) acc[t][u][v] = 0.f;

    auto issue_chunk = [&](int c) {
        const uint32_t st = sb + (c & 3) * STAGEB;
        const uint32_t so = p_row * ROWB + p_ch * 16;
        const size_t ga = (size_t)(m0 + p_row) * 1024 + c * 32 + p_ch * 8;
        const size_t gb = (size_t)(n0 + p_row) * 1024 + c * 32 + p_ch * 8;
        cp16(st + AHI_O + so, Ahi + ga);
        cp16(st + ALO_O + so, Alo + ga);
        cp16(st + BHI_O + so, Bhi + gb);
        cp16(st + BLO_O + so, Blo + gb);
    };

    issue_chunk(0); CP_COMMIT();
    issue_chunk(1); CP_COMMIT();
    issue_chunk(2); CP_COMMIT();

    for (int c = 0; c < 32; ++c) {
        CP_WAIT(2);
        __syncthreads();
        if (c + 3 < 32) issue_chunk(c + 3);
        CP_COMMIT();

        const uint32_t sbase = sb + (c & 3) * STAGEB;
#pragma unroll
        for (int ks = 0; ks < 2; ++ks) {
            const uint32_t ko = ks * 32;
            uint32_t ah[2][4], al[2][4], bh[2][4], bl[2][4];
#pragma unroll
            for (int t = 0; t < 2; ++t) {
                uint32_t ra = (wm + t * 16) * ROWB + lm_off + ko;
                ldm4(ah[t], sbase + AHI_O + ra);
                ldm4(al[t], sbase + ALO_O + ra);
            }
#pragma unroll
            for (int p = 0; p < 2; ++p) {
                uint32_t rb = (wn + p * 16) * ROWB + lm_off + ko;
                ldm4(bh[p], sbase + BHI_O + rb);
                ldm4(bl[p], sbase + BLO_O + rb);
            }
#pragma unroll
            for (int t = 0; t < 2; ++t)
#pragma unroll
                for (int p = 0; p < 2; ++p) {
                    mma_f16(acc[t][p * 2 + 0], ah[t], bh[p][0], bh[p][2]);
                    mma_f16(acc[t][p * 2 + 1], ah[t], bh[p][1], bh[p][3]);
                    mma_f16(acc[t][p * 2 + 0], ah[t], bl[p][0], bl[p][2]);
                    mma_f16(acc[t][p * 2 + 1], ah[t], bl[p][1], bl[p][3]);
                    mma_f16(acc[t][p * 2 + 0], al[t], bh[p][0], bh[p][2]);
                    mma_f16(acc[t][p * 2 + 1], al[t], bh[p][1], bh[p][3]);
                }
        }
        __syncthreads();    // all warps done with stage c before it is refilled
    }

    // Epilogue
#pragma unroll
    for (int t = 0; t < 2; ++t) {
        const int r0 = m0 + wm + t * 16 + grp;
#pragma unroll
        for (int u = 0; u < 4; ++u) {
            const int col = n0 + wn + u * 8 + qid * 2;
            const float b0v = bias[col], b1v = bias[col + 1];
            float v00 = (acc[t][u][0] + b0v) * scale;
            float v01 = (acc[t][u][1] + b1v) * scale;
            float v10 = (acc[t][u][2] + b0v) * scale;
            float v11 = (acc[t][u][3] + b1v) * scale;
            if (Chi) {
                __half h00 = __float2half_rn(v00), h01 = __float2half_rn(v01);
                __half h10 = __float2half_rn(v10), h11 = __float2half_rn(v11);
                *(uint32_t*)(Chi + (size_t)r0 * 1024 + col) = pack2h(h00, h01);
                *(uint32_t*)(Chi + (size_t)(r0 + 8) * 1024 + col) = pack2h(h10, h11);
                if (Clo) {
                    *(uint32_t*)(Clo + (size_t)r0 * 1024 + col) =
                        pack2h(__float2half_rn(v00 - __half2float(h00)),
                               __float2half_rn(v01 - __half2float(h01)));
                    *(uint32_t*)(Clo + (size_t)(r0 + 8) * 1024 + col) =
                        pack2h(__float2half_rn(v10 - __half2float(h10)),
                               __float2half_rn(v11 - __half2float(h11)));
                }
            } else {
                float2 o0 = {v00, v01}, o1 = {v10, v11};
                *(float2*)(C + (size_t)r0 * 1024 + col) = o0;
                *(float2*)(C + (size_t)(r0 + 8) * 1024 + col) = o1;
            }
        }
    }
}

// ---------------------------------------------------------------------------
// Flash attention: fp16-single QK^T, fp16-single P x split-fp16 V.
// 256 threads = 8 warps; warp w owns rows 16w..16w+15 of a 128-row q-tile.
// ---------------------------------------------------------------------------
#define AROWB  144
#define A_Q    0
#define A_ST0  18432
#define A_STB  27648                    // K + Vhi + Vlo, 64 x 144 each
#define A_K    0
#define A_VHI  9216
#define A_VLO  18432
#define ATTN_SMEM_BYTES (A_ST0 + 2 * A_STB)

__global__ __launch_bounds__(256)
void attn_mma_kernel(const float* __restrict__ ab, const float* __restrict__ abkv)
{
    extern __shared__ char sm[];
    const uint32_t sb = smem_u32(sm);
    const int tid = threadIdx.x, lane = tid & 31, wid = tid >> 5;
    const int grp = lane >> 2, qid = lane & 3;
    const int b = blockIdx.z, h = blockIdx.y, q0 = blockIdx.x * 128;
    const int wr = wid * 16;
    const int lm_off = (lane & 15) * AROWB + ((lane >> 4) << 4);

    // Q tile: 128 x 64 fp16 = 1024 x 16B
#pragma unroll
    for (int i = 0; i < 4; ++i) {
        int idx = i * 256 + tid;
        int row = idx >> 3, ch = idx & 7;
        cp16(sb + A_Q + row * AROWB + ch * 16,
             g_Qh + (size_t)(b * SS + q0 + row) * 1024 + h * 64 + ch * 8);
    }

    auto issue_tile = [&](int kt) {
        const uint32_t st = sb + A_ST0 + (kt & 1) * A_STB;
        const int k0 = kt * 64;
#pragma unroll
        for (int i = 0; i < 6; ++i) {
            int idx = i * 256 + tid;                 // 0..1535
            int arr = idx >> 9;                      // 0=K 1=Vhi 2=Vlo
            int rem = idx & 511;
            int row = rem >> 3, ch = rem & 7;
            const __half* g = (arr == 0 ? g_Kh : arr == 1 ? g_Vhi : g_Vlo)
                + (size_t)(b * SS + k0 + row) * 1024 + h * 64 + ch * 8;
            cp16(st + (arr == 0 ? A_K : arr == 1 ? A_VHI : A_VLO) + row * AROWB + ch * 16, g);
        }
    };

    issue_tile(0); CP_COMMIT();     // G0 = Q + tile0
    issue_tile(1); CP_COMMIT();     // G1
    CP_WAIT(1);
    __syncthreads();

    // Q fragments
    uint32_t qf[4][4];
#pragma unroll
    for (int ks = 0; ks < 4; ++ks)
        ldm4(qf[ks], sb + A_Q + wr * AROWB + lm_off + ks * 32);

    float oacc[8][4];
#pragma unroll
    for (int f = 0; f < 8; ++f)
#pragma unroll
        for (int v = 0; v < 4; ++v) oacc[f][v] = 0.f;
    float m0 = -1e30f, m1 = -1e30f, l0 = 0.f, l1 = 0.f;

    const float* abp   = ab + (size_t)(q0 + wr + grp) * SS + qid * 2;
    const float* abkvp = abkv + b * SS + qid * 2;

    for (int kt = 0; kt < 32; ++kt) {
        const uint32_t st = sb + A_ST0 + (kt & 1) * A_STB;
        const int k0 = kt * 64;

        CP_WAIT(1);
        __syncthreads();

        // ---- S = Q K^T (1-term fp16) ----
        float sacc[8][4];
#pragma unroll
        for (int f = 0; f < 8; ++f)
#pragma unroll
            for (int v = 0; v < 4; ++v) sacc[f][v] = 0.f;

#pragma unroll
        for (int ks = 0; ks < 4; ++ks) {
            uint32_t kh[4][4];
#pragma unroll
            for (int j = 0; j < 4; ++j)
                ldm4(kh[j], st + A_K + (j * 16) * AROWB + lm_off + ks * 32);
#pragma unroll
            for (int j = 0; j < 4; ++j) {
                mma_f16(sacc[2 * j + 0], qf[ks], kh[j][0], kh[j][2]);
                mma_f16(sacc[2 * j + 1], qf[ks], kh[j][1], kh[j][3]);
            }
        }

        // ---- bias + online softmax ----
        float mx0 = -1e30f, mx1 = -1e30f;
#pragma unroll
        for (int f = 0; f < 8; ++f) {
            float2 bk = *(const float2*)(abkvp + k0 + f * 8);
            float2 b0 = *(const float2*)(abp + k0 + f * 8);
            float2 b1 = *(const float2*)(abp + 8 * SS + k0 + f * 8);
            sacc[f][0] += b0.x + bk.x; sacc[f][1] += b0.y + bk.y;
            sacc[f][2] += b1.x + bk.x; sacc[f][3] += b1.y + bk.y;
            mx0 = fmaxf(mx0, fmaxf(sacc[f][0], sacc[f][1]));
            mx1 = fmaxf(mx1, fmaxf(sacc[f][2], sacc[f][3]));
        }
        mx0 = fmaxf(mx0, __shfl_xor_sync(0xffffffffu, mx0, 1));
        mx0 = fmaxf(mx0, __shfl_xor_sync(0xffffffffu, mx0, 2));
        mx1 = fmaxf(mx1, __shfl_xor_sync(0xffffffffu, mx1, 1));
        mx1 = fmaxf(mx1, __shfl_xor_sync(0xffffffffu, mx1, 2));

        const float mn0 = fmaxf(m0, mx0), mn1 = fmaxf(m1, mx1);
        const float e0 = __expf(m0 - mn0), e1 = __expf(m1 - mn1);
        m0 = mn0; m1 = mn1;

        float rs0 = 0.f, rs1 = 0.f;
        uint32_t aP[4][4];
#pragma unroll
        for (int j = 0; j < 4; ++j) {
            float p[8];
            p[0] = __expf(sacc[2 * j][0] - mn0);
            p[1] = __expf(sacc[2 * j][1] - mn0);
            p[2] = __expf(sacc[2 * j][2] - mn1);
            p[3] = __expf(sacc[2 * j][3] - mn1);
            p[4] = __expf(sacc[2 * j + 1][0] - mn0);
            p[5] = __expf(sacc[2 * j + 1][1] - mn0);
            p[6] = __expf(sacc[2 * j + 1][2] - mn1);
            p[7] = __expf(sacc[2 * j + 1][3] - mn1);
            rs0 += p[0] + p[1] + p[4] + p[5];
            rs1 += p[2] + p[3] + p[6] + p[7];
            aP[j][0] = pack2h(__float2half_rn(p[0]), __float2half_rn(p[1]));
            aP[j][1] = pack2h(__float2half_rn(p[2]), __float2half_rn(p[3]));
            aP[j][2] = pack2h(__float2half_rn(p[4]), __float2half_rn(p[5]));
            aP[j][3] = pack2h(__float2half_rn(p[6]), __float2half_rn(p[7]));
        }
        l0 = l0 * e0 + rs0;
        l1 = l1 * e1 + rs1;
#pragma unroll
        for (int f = 0; f < 8; ++f) {
            oacc[f][0] *= e0; oacc[f][1] *= e0;
            oacc[f][2] *= e1; oacc[f][3] *= e1;
        }

        // ---- O += P (Vhi + Vlo) ----
#pragma unroll
        for (int j = 0; j < 4; ++j) {
            uint32_t vh[4][4], vl[4][4];
#pragma unroll
            for (int jj = 0; jj < 4; ++jj) {
                uint32_t rb = (j * 16 + (lane & 15)) * AROWB + jj * 32 + ((lane >> 4) << 4);
                ldm4t(vh[jj], st + A_VHI + rb);
                ldm4t(vl[jj], st + A_VLO + rb);
            }
#pragma unroll
            for (int jj = 0; jj < 4; ++jj) {
                mma_f16(oacc[2 * jj + 0], aP[j], vh[jj][0], vh[jj][1]);
                mma_f16(oacc[2 * jj + 1], aP[j], vh[jj][2], vh[jj][3]);
                mma_f16(oacc[2 * jj + 0], aP[j], vl[jj][0], vl[jj][1]);
                mma_f16(oacc[2 * jj + 1], aP[j], vl[jj][2], vl[jj][3]);
            }
        }

        __syncthreads();
        if (kt + 2 < 32) issue_tile(kt + 2);
        CP_COMMIT();
    }

    // ---- normalize + write split-fp16 X ----
    l0 += __shfl_xor_sync(0xffffffffu, l0, 1);
    l0 += __shfl_xor_sync(0xffffffffu, l0, 2);
    l1 += __shfl_xor_sync(0xffffffffu, l1, 1);
    l1 += __shfl_xor_sync(0xffffffffu, l1, 2);
    const float inv0 = 1.f / l0, inv1 = 1.f / l1;

    const size_t xo = (size_t)(b * SS + q0 + wr + grp) * 1024 + h * 64 + qid * 2;
#pragma unroll
    for (int f = 0; f < 8; ++f) {
        float v00 = oacc[f][0] * inv0, v01 = oacc[f][1] * inv0;
        float v10 = oacc[f][2] * inv1, v11 = oacc[f][3] * inv1;
        __half h00 = __float2half_rn(v00), h01 = __float2half_rn(v01);
        __half h10 = __float2half_rn(v10), h11 = __float2half_rn(v11);
        *(uint32_t*)(g_Xhi + xo + f * 8) = pack2h(h00, h01);
        *(uint32_t*)(g_Xhi + xo + (size_t)8 * 1024 + f * 8) = pack2h(h10, h11);
        *(uint32_t*)(g_Xlo + xo + f * 8) =
            pack2h(__float2half_rn(v00 - __half2float(h00)),
                   __float2half_rn(v01 - __half2float(h01)));
        *(uint32_t*)(g_Xlo + xo + (size_t)8 * 1024 + f * 8) =
            pack2h(__float2half_rn(v10 - __half2float(h10)),
                   __float2half_rn(v11 - __half2float(h11)));
    }
}

// ---------------------------------------------------------------------------
extern "C" void kernel_launch(void* const* d_in, const int* in_sizes, int n_in,
                              void* d_out, int out_size)
{
    const float* x    = (const float*)d_in[0];
    const float* pq   = (const float*)d_in[1];
    const float* pk   = (const float*)d_in[2];
    const float* pv   = (const float*)d_in[3];
    const float* ab   = (const float*)d_in[4];
    const float* abkv = (const float*)d_in[5];
    const float* bq   = (const float*)d_in[7];
    const float* bk   = (const float*)d_in[9];
    const float* bv   = (const float*)d_in[11];
    const float* wo   = (const float*)d_in[12];
    const float* bo   = (const float*)d_in[13];
    const float* wq   = (const float*)d_in[6];
    const float* wk   = (const float*)d_in[8];
    const float* wv   = (const float*)d_in[10];
    float* out = (float*)d_out;

    __half *Whi, *Wlo, *Ahi, *Alo, *Qh, *Kh, *Vhi, *Vlo, *Xhi, *Xlo;
    cudaGetSymbolAddress((void**)&Whi, g_Whi);
    cudaGetSymbolAddress((void**)&Wlo, g_Wlo);
    cudaGetSymbolAddress((void**)&Ahi, g_Ahi);
    cudaGetSymbolAddress((void**)&Alo, g_Alo);
    cudaGetSymbolAddress((void**)&Qh,  g_Qh);
    cudaGetSymbolAddress((void**)&Kh,  g_Kh);
    cudaGetSymbolAddress((void**)&Vhi, g_Vhi);
    cudaGetSymbolAddress((void**)&Vlo, g_Vlo);
    cudaGetSymbolAddress((void**)&Xhi, g_Xhi);
    cudaGetSymbolAddress((void**)&Xlo, g_Xlo);
    const size_t WSZ = (size_t)1024 * 1024;
    const size_t ASZ = (size_t)8192 * 1024;

    dim3 pgrid(32, 32), pblk(32, 8);
    prep_w_kernel<<<pgrid, pblk>>>(wq, Whi + 0 * WSZ, Wlo + 0 * WSZ);
    prep_w_kernel<<<pgrid, pblk>>>(wk, Whi + 1 * WSZ, Wlo + 1 * WSZ);
    prep_w_kernel<<<pgrid, pblk>>>(wv, Whi + 2 * WSZ, Wlo + 2 * WSZ);
    prep_w_kernel<<<pgrid, pblk>>>(wo, Whi + 3 * WSZ, Wlo + 3 * WSZ);
    prep_act_kernel<<<8192, 256>>>(x, pq, pk, pv);

    cudaFuncSetAttribute(gemm_mma_kernel, cudaFuncAttributeMaxDynamicSharedMemorySize,
                         GEMM_SMEM_BYTES);
    dim3 ggrid(1024 / 128, 8192 / 128);

    // Q: fp16 single (scale 1/8). K: fp16 single. V: fp16 split.
    gemm_mma_kernel<<<ggrid, 512, GEMM_SMEM_BYTES>>>(Ahi + 0 * ASZ, Alo + 0 * ASZ,
        Whi + 0 * WSZ, Wlo + 0 * WSZ, bq, nullptr, Qh, nullptr, 0.125f);
    gemm_mma_kernel<<<ggrid, 512, GEMM_SMEM_BYTES>>>(Ahi + 1 * ASZ, Alo + 1 * ASZ,
        Whi + 1 * WSZ, Wlo + 1 * WSZ, bk, nullptr, Kh, nullptr, 1.0f);
    gemm_mma_kernel<<<ggrid, 512, GEMM_SMEM_BYTES>>>(Ahi + 2 * ASZ, Alo + 2 * ASZ,
        Whi + 2 * WSZ, Wlo + 2 * WSZ, bv, nullptr, Vhi, Vlo, 1.0f);

    cudaFuncSetAttribute(attn_mma_kernel, cudaFuncAttributeMaxDynamicSharedMemorySize,
                         ATTN_SMEM_BYTES);
    attn_mma_kernel<<<dim3(SS / 128, HH, BB), 256, ATTN_SMEM_BYTES>>>(ab, abkv);

    gemm_mma_kernel<<<ggrid, 512, GEMM_SMEM_BYTES>>>(Xhi, Xlo,
        Whi + 3 * WSZ, Wlo + 3 * WSZ, bo, out, nullptr, nullptr, 1.0f);
}